// round 3
// baseline (speedup 1.0000x reference)
#include <cuda_runtime.h>
#include <cstdint>
#include <cstddef>

#define DEV __device__ __forceinline__

// ---------------- problem constants ----------------
static constexpr int BB = 32;
static constexpr int SEQ = 2048;
static constexpr int DD = 1024;    // K
static constexpr int SZ = 1024;    // SIZE

static constexpr int M_TILE = 128;
static constexpr int N_TILE = 256;
static constexpr int PASSES = SZ / N_TILE;   // 4
static constexpr int K_CHUNK = 32;
static constexpr int NCHUNK = DD / K_CHUNK;  // 32
static constexpr int THREADS = 512;          // 16 warps: 2m x 8n, warp tile 64x32
static constexpr int KPAD = 36;              // floats per smem row (144 B, conflict-free)

// smem layout in floats
static constexpr int S_A0 = 0;
static constexpr int A_FLOATS = M_TILE * KPAD;        // 4608
static constexpr int S_A1 = S_A0 + A_FLOATS;
static constexpr int S_B0 = S_A1 + A_FLOATS;
static constexpr int B_FLOATS = N_TILE * KPAD;        // 9216
static constexpr int S_B1 = S_B0 + B_FLOATS;
static constexpr int S_T2 = S_B1 + B_FLOATS;
static constexpr int S_V  = S_T2 + SZ;
static constexpr int S_PART = S_V + SZ;
static constexpr int SMEM_FLOATS = S_PART + M_TILE;
static constexpr int SMEM_BYTES = SMEM_FLOATS * 4;    // ~119 KB

// scratch: tf32-rounded WO + term2 (X is rounded in-kernel during staging)
__device__ float g_WOr[(size_t)SZ * DD];   // 4 MB
__device__ float g_term2[BB * SZ];

// ---------------- helpers ----------------
DEV uint32_t smem_u32(const void* p) {
    uint32_t a;
    asm("{ .reg .u64 t; cvta.to.shared.u64 t, %1; cvt.u32.u64 %0, t; }" : "=r"(a) : "l"(p));
    return a;
}
DEV void cp16(uint32_t s, const void* g) {
    asm volatile("cp.async.cg.shared.global [%0], [%1], 16;" :: "r"(s), "l"(g));
}
DEV void cp_commit() { asm volatile("cp.async.commit_group;" ::: "memory"); }
template <int N> DEV void cp_wait() { asm volatile("cp.async.wait_group %0;" :: "n"(N) : "memory"); }

DEV float tanh_fast(float x) {
    float y;
    asm("tanh.approx.f32 %0, %1;" : "=f"(y) : "f"(x));
    return y;
}
DEV uint32_t rna_tf32(uint32_t b) {
    return (b + 0xFFFu + ((b >> 13) & 1u)) & 0xFFFFE000u;
}

DEV void mma_tf32(float* d, const uint32_t* a, const uint32_t* b) {
    asm volatile(
        "mma.sync.aligned.m16n8k8.row.col.f32.tf32.tf32.f32 "
        "{%0,%1,%2,%3}, {%4,%5,%6,%7}, {%8,%9}, {%0,%1,%2,%3};"
        : "+f"(d[0]), "+f"(d[1]), "+f"(d[2]), "+f"(d[3])
        : "r"(a[0]), "r"(a[1]), "r"(a[2]), "r"(a[3]), "r"(b[0]), "r"(b[1]));
}

// A staging: LDG.128 from X, rna-round to tf32, STS.128 into KPAD rows.
// [128 rows x 32 floats] -> 1024 float4 transfers / 512 threads = 2 iters.
DEV void stage_A(float* sdst, const float* gsrc, int tid) {
    const int total = M_TILE * 8;
#pragma unroll
    for (int it = 0; it < 2; it++) {
        const int gidx = tid + it * THREADS;
        if (gidx < total) {
            const int r = gidx >> 3, c = gidx & 7;
            uint4 u = *(const uint4*)(gsrc + (size_t)r * DD + c * 4);
            u.x = rna_tf32(u.x); u.y = rna_tf32(u.y);
            u.z = rna_tf32(u.z); u.w = rna_tf32(u.w);
            *(uint4*)(sdst + r * KPAD + c * 4) = u;
        }
    }
}

// B staging: cp.async from pre-rounded WOr. [256 rows x 32 floats].
DEV void stage_B(float* sdst, const float* gsrc, int tid) {
    const uint32_t sb = smem_u32(sdst);
    const int total = N_TILE * 8;
#pragma unroll
    for (int it = 0; it < 4; it++) {
        const int gidx = tid + it * THREADS;
        const int r = gidx >> 3, c = gidx & 7;
        if (gidx < total)
            cp16(sb + (uint32_t)(r * KPAD + c * 4) * 4u, gsrc + (size_t)r * DD + c * 4);
    }
}

// ---------------- prepass: tf32-rna rounding of WO ----------------
__global__ void round_kernel(const float* __restrict__ src, float* __restrict__ dst, int n4) {
    int i = blockIdx.x * blockDim.x + threadIdx.x;
    if (i >= n4) return;
    uint4 u = ((const uint4*)src)[i];
    u.x = rna_tf32(u.x); u.y = rna_tf32(u.y); u.z = rna_tf32(u.z); u.w = rna_tf32(u.w);
    ((uint4*)dst)[i] = u;
}

// ---------------- term2 = WG @ g  (exact fp32 SIMT) ----------------
__global__ void term2_kernel(const float* __restrict__ WG, const float* __restrict__ g) {
    __shared__ float4 gs[256];
    const int b = blockIdx.y;
    gs[threadIdx.x] = ((const float4*)(g + (size_t)b * DD))[threadIdx.x];
    __syncthreads();
    const int w = threadIdx.x >> 5, l = threadIdx.x & 31;
    const int n = blockIdx.x * 8 + w;
    const float4* wg4 = (const float4*)(WG + (size_t)n * DD);
    float s = 0.f;
#pragma unroll
    for (int i = 0; i < 8; i++) {
        float4 a = wg4[l + 32 * i];
        float4 gg = gs[l + 32 * i];
        s += a.x * gg.x + a.y * gg.y + a.z * gg.z + a.w * gg.w;
    }
#pragma unroll
    for (int o = 16; o; o >>= 1) s += __shfl_xor_sync(0xFFFFFFFFu, s, o);
    if (l == 0) g_term2[b * SZ + n] = s;
}

// ---------------- fused GEMM(tf32 mma.sync) + tanh + v-dot ----------------
__global__ __launch_bounds__(THREADS, 1)
void fused_kernel(const float* __restrict__ X, const float* __restrict__ v,
                  float* __restrict__ out) {
    extern __shared__ float smem[];
    const int tid = threadIdx.x;
    const int lane = tid & 31, wid = tid >> 5;
    const int wm = wid >> 3, wn = wid & 7;      // 2 x 8 warp grid; warp tile 64x32
    const int m0 = blockIdx.x * M_TILE;
    const int bidx = m0 >> 11;                  // batch index (2048 rows per batch)

    float* t2s = smem + S_T2;
    float* vs  = smem + S_V;
    float* part = smem + S_PART;

    for (int i = tid; i < SZ; i += THREADS) {
        t2s[i] = g_term2[bidx * SZ + i];
        vs[i] = v[i];
    }
    for (int i = tid; i < M_TILE; i += THREADS) part[i] = 0.f;
    __syncthreads();

    const float* Xbase = X + (size_t)m0 * DD;

    float racc[8];
#pragma unroll
    for (int j = 0; j < 8; j++) racc[j] = 0.f;

    const int ar = lane >> 2;   // group id (row within fragment)
    const int ak = lane & 3;    // thread-in-group (k / col pair)

#pragma unroll 1
    for (int p = 0; p < PASSES; p++) {
        const float* Wbase = g_WOr + (size_t)p * N_TILE * DD;

        float acc[4][4][4];
#pragma unroll
        for (int mt = 0; mt < 4; mt++)
#pragma unroll
            for (int nt = 0; nt < 4; nt++)
#pragma unroll
                for (int q = 0; q < 4; q++) acc[mt][nt][q] = 0.f;

        // prologue: chunk 0 -> buffer 0
        stage_A(smem + S_A0, Xbase, tid);
        stage_B(smem + S_B0, Wbase, tid);
        cp_commit();

#pragma unroll 1
        for (int c = 0; c < NCHUNK; c++) {
            if (c + 1 < NCHUNK) {
                float* an = smem + (((c + 1) & 1) ? S_A1 : S_A0);
                float* bn = smem + (((c + 1) & 1) ? S_B1 : S_B0);
                stage_A(an, Xbase + (c + 1) * K_CHUNK, tid);
                stage_B(bn, Wbase + (c + 1) * K_CHUNK, tid);
                cp_commit();
                cp_wait<1>();
            } else {
                cp_wait<0>();
            }
            __syncthreads();

            const uint32_t* As = (const uint32_t*)(smem + ((c & 1) ? S_A1 : S_A0));
            const uint32_t* Bs = (const uint32_t*)(smem + ((c & 1) ? S_B1 : S_B0));

#pragma unroll
            for (int k8 = 0; k8 < 4; k8++) {
                const int ko = k8 * 8;
                uint32_t a[4][4], b[4][2];
#pragma unroll
                for (int mt = 0; mt < 4; mt++) {
                    const int r0 = (wm * 64 + mt * 16 + ar) * KPAD + ko + ak;
                    a[mt][0] = As[r0];
                    a[mt][1] = As[r0 + 8 * KPAD];
                    a[mt][2] = As[r0 + 4];
                    a[mt][3] = As[r0 + 8 * KPAD + 4];
                }
#pragma unroll
                for (int nt = 0; nt < 4; nt++) {
                    const int nb = (wn * 32 + nt * 8 + ar) * KPAD + ko + ak;
                    b[nt][0] = Bs[nb];
                    b[nt][1] = Bs[nb + 4];
                }
#pragma unroll
                for (int mt = 0; mt < 4; mt++)
#pragma unroll
                    for (int nt = 0; nt < 4; nt++)
                        mma_tf32(acc[mt][nt], a[mt], b[nt]);
            }
            __syncthreads();
        }

        // ---- epilogue for this N pass: acc -> tanh -> v-dot row partials ----
#pragma unroll
        for (int mt = 0; mt < 4; mt++) {
#pragma unroll
            for (int nt = 0; nt < 4; nt++) {
                const int gn = p * N_TILE + wn * 32 + nt * 8 + 2 * ak;
                const float v0 = vs[gn], v1 = vs[gn + 1];
                const float t20 = t2s[gn], t21 = t2s[gn + 1];
                racc[mt * 2] += v0 * tanh_fast(acc[mt][nt][0] + t20)
                              + v1 * tanh_fast(acc[mt][nt][1] + t21);
                racc[mt * 2 + 1] += v0 * tanh_fast(acc[mt][nt][2] + t20)
                                  + v1 * tanh_fast(acc[mt][nt][3] + t21);
            }
        }
    }

    // reduce over the 4 lanes of each column group (ak bits of lane)
#pragma unroll
    for (int j = 0; j < 8; j++) {
        racc[j] += __shfl_xor_sync(0xFFFFFFFFu, racc[j], 1);
        racc[j] += __shfl_xor_sync(0xFFFFFFFFu, racc[j], 2);
    }
    if (ak == 0) {
#pragma unroll
        for (int j = 0; j < 8; j++) {
            const int row = wm * 64 + (j >> 1) * 16 + ar + (j & 1) * 8;
            atomicAdd(&part[row], racc[j]);
        }
    }
    __syncthreads();
    if (tid < M_TILE) out[m0 + tid] = part[tid];
}

// ---------------- launch ----------------
extern "C" void kernel_launch(void* const* d_in, const int* in_sizes, int n_in,
                              void* d_out, int out_size) {
    const float* X  = (const float*)d_in[0];   // inputs [B,S,D]
    const float* g  = (const float*)d_in[1];   // g [B,D]
    const float* WO = (const float*)d_in[2];   // WO [SIZE,D]
    const float* WG = (const float*)d_in[3];   // WG [SIZE,D]
    const float* v  = (const float*)d_in[4];   // v [1,SIZE]
    float* out = (float*)d_out;

    float* WOr; cudaGetSymbolAddress((void**)&WOr, g_WOr);

    cudaFuncSetAttribute(fused_kernel, cudaFuncAttributeMaxDynamicSharedMemorySize, SMEM_BYTES);

    const int nW4 = SZ * DD / 4;
    round_kernel<<<nW4 / 256, 256>>>(WO, WOr, nW4);
    term2_kernel<<<dim3(SZ / 8, BB), 256>>>(WG, g);

    fused_kernel<<<(BB * SEQ) / M_TILE, THREADS, SMEM_BYTES>>>(X, v, out);
}

// round 5
// speedup vs baseline: 1.0145x; 1.0145x over previous
#include <cuda_runtime.h>
#include <cstdint>
#include <cstddef>

#define DEV __device__ __forceinline__

// ---------------- problem constants ----------------
static constexpr int BB = 32;
static constexpr int SEQ = 2048;
static constexpr int DD = 1024;    // K
static constexpr int SZ = 1024;    // SIZE

static constexpr int M_TILE = 128;
static constexpr int N_TILE = 256;
static constexpr int PASSES = SZ / N_TILE;   // 4
static constexpr int K_CHUNK = 32;
static constexpr int NCHUNK = DD / K_CHUNK;  // 32
static constexpr int THREADS = 512;          // 16 warps: 2m x 8n, warp tile 64x32
static constexpr int KPAD = 36;              // floats per smem row (144 B, conflict-free)

// smem layout in floats
static constexpr int S_A0 = 0;
static constexpr int A_FLOATS = M_TILE * KPAD;        // 4608
static constexpr int S_A1 = S_A0 + A_FLOATS;
static constexpr int S_B0 = S_A1 + A_FLOATS;
static constexpr int B_FLOATS = N_TILE * KPAD;        // 9216
static constexpr int S_B1 = S_B0 + B_FLOATS;
static constexpr int S_T2 = S_B1 + B_FLOATS;
static constexpr int S_V  = S_T2 + SZ;
static constexpr int S_PART = S_V + SZ;
static constexpr int SMEM_FLOATS = S_PART + M_TILE;
static constexpr int SMEM_BYTES = SMEM_FLOATS * 4;    // ~119 KB

// scratch: tf32-rounded copies + term2
__device__ float g_Xr[(size_t)BB * SEQ * DD];   // 256 MB
__device__ float g_WOr[(size_t)SZ * DD];        // 4 MB
__device__ float g_term2[BB * SZ];

// ---------------- helpers ----------------
DEV uint32_t smem_u32(const void* p) {
    uint32_t a;
    asm("{ .reg .u64 t; cvta.to.shared.u64 t, %1; cvt.u32.u64 %0, t; }" : "=r"(a) : "l"(p));
    return a;
}
DEV void cp16(uint32_t s, const void* g) {
    asm volatile("cp.async.cg.shared.global [%0], [%1], 16;" :: "r"(s), "l"(g));
}
DEV void cp_commit() { asm volatile("cp.async.commit_group;" ::: "memory"); }
template <int N> DEV void cp_wait() { asm volatile("cp.async.wait_group %0;" :: "n"(N) : "memory"); }

DEV float tanh_fast(float x) {
    float y;
    asm("tanh.approx.f32 %0, %1;" : "=f"(y) : "f"(x));
    return y;
}
DEV uint32_t rna_tf32(uint32_t b) {
    return (b + 0xFFFu + ((b >> 13) & 1u)) & 0xFFFFE000u;
}

DEV void mma_tf32(float* d, const uint32_t* a, const uint32_t* b) {
    asm volatile(
        "mma.sync.aligned.m16n8k8.row.col.f32.tf32.tf32.f32 "
        "{%0,%1,%2,%3}, {%4,%5,%6,%7}, {%8,%9}, {%0,%1,%2,%3};"
        : "+f"(d[0]), "+f"(d[1]), "+f"(d[2]), "+f"(d[3])
        : "r"(a[0]), "r"(a[1]), "r"(a[2]), "r"(a[3]), "r"(b[0]), "r"(b[1]));
}

// A staging via cp.async: [128 rows x 32 floats], 1024 xfers / 512 thr = 2 iters
DEV void stage_A(float* sdst, const float* gsrc, int tid) {
    const uint32_t sb = smem_u32(sdst);
#pragma unroll
    for (int it = 0; it < 2; it++) {
        const int gidx = tid + it * THREADS;
        const int r = gidx >> 3, c = gidx & 7;
        cp16(sb + (uint32_t)(r * KPAD + c * 4) * 4u, gsrc + (size_t)r * DD + c * 4);
    }
}
// B staging via cp.async: [256 rows x 32 floats], 2048 xfers / 512 thr = 4 iters
DEV void stage_B(float* sdst, const float* gsrc, int tid) {
    const uint32_t sb = smem_u32(sdst);
#pragma unroll
    for (int it = 0; it < 4; it++) {
        const int gidx = tid + it * THREADS;
        const int r = gidx >> 3, c = gidx & 7;
        cp16(sb + (uint32_t)(r * KPAD + c * 4) * 4u, gsrc + (size_t)r * DD + c * 4);
    }
}

// ---------------- prepass: tf32-rna rounding ----------------
__global__ void round_kernel(const float* __restrict__ src, float* __restrict__ dst, int n4) {
    int i = blockIdx.x * blockDim.x + threadIdx.x;
    if (i >= n4) return;
    uint4 u = ((const uint4*)src)[i];
    u.x = rna_tf32(u.x); u.y = rna_tf32(u.y); u.z = rna_tf32(u.z); u.w = rna_tf32(u.w);
    ((uint4*)dst)[i] = u;
}

// ---------------- term2 = WG @ g  (exact fp32 SIMT) ----------------
__global__ void term2_kernel(const float* __restrict__ WG, const float* __restrict__ g) {
    __shared__ float4 gs[256];
    const int b = blockIdx.y;
    gs[threadIdx.x] = ((const float4*)(g + (size_t)b * DD))[threadIdx.x];
    __syncthreads();
    const int w = threadIdx.x >> 5, l = threadIdx.x & 31;
    const int n = blockIdx.x * 8 + w;
    const float4* wg4 = (const float4*)(WG + (size_t)n * DD);
    float s = 0.f;
#pragma unroll
    for (int i = 0; i < 8; i++) {
        float4 a = wg4[l + 32 * i];
        float4 gg = gs[l + 32 * i];
        s += a.x * gg.x + a.y * gg.y + a.z * gg.z + a.w * gg.w;
    }
#pragma unroll
    for (int o = 16; o; o >>= 1) s += __shfl_xor_sync(0xFFFFFFFFu, s, o);
    if (l == 0) g_term2[b * SZ + n] = s;
}

// ---------------- fused GEMM(tf32 mma.sync) + tanh + v-dot ----------------
__global__ __launch_bounds__(THREADS, 1)
void fused_kernel(const float* __restrict__ v, float* __restrict__ out) {
    extern __shared__ float smem[];
    const int tid = threadIdx.x;
    const int lane = tid & 31, wid = tid >> 5;
    const int wm = wid >> 3, wn = wid & 7;      // 2 x 8 warp grid; warp tile 64x32
    const int m0 = blockIdx.x * M_TILE;
    const int bidx = m0 >> 11;                  // batch index (2048 rows per batch)

    float* t2s = smem + S_T2;
    float* vs  = smem + S_V;
    float* part = smem + S_PART;

    for (int i = tid; i < SZ; i += THREADS) {
        t2s[i] = g_term2[bidx * SZ + i];
        vs[i] = v[i];
    }
    for (int i = tid; i < M_TILE; i += THREADS) part[i] = 0.f;
    __syncthreads();

    const float* Xbase = g_Xr + (size_t)m0 * DD;

    float racc[8];
#pragma unroll
    for (int j = 0; j < 8; j++) racc[j] = 0.f;

    const int ar = lane >> 2;   // group id (row within fragment)
    const int ak = lane & 3;    // thread-in-group (k / col pair)

#pragma unroll 1
    for (int p = 0; p < PASSES; p++) {
        const float* Wbase = g_WOr + (size_t)p * N_TILE * DD;

        float acc[4][4][4];
#pragma unroll
        for (int mt = 0; mt < 4; mt++)
#pragma unroll
            for (int nt = 0; nt < 4; nt++)
#pragma unroll
                for (int q = 0; q < 4; q++) acc[mt][nt][q] = 0.f;

        // prologue: chunk 0 -> buffer 0
        stage_A(smem + S_A0, Xbase, tid);
        stage_B(smem + S_B0, Wbase, tid);
        cp_commit();

#pragma unroll 1
        for (int c = 0; c < NCHUNK; c++) {
            if (c + 1 < NCHUNK) {
                float* an = smem + (((c + 1) & 1) ? S_A1 : S_A0);
                float* bn = smem + (((c + 1) & 1) ? S_B1 : S_B0);
                stage_A(an, Xbase + (c + 1) * K_CHUNK, tid);
                stage_B(bn, Wbase + (c + 1) * K_CHUNK, tid);
                cp_commit();
                cp_wait<1>();
            } else {
                cp_wait<0>();
            }
            __syncthreads();

            const uint32_t* As = (const uint32_t*)(smem + ((c & 1) ? S_A1 : S_A0));
            const uint32_t* Bs = (const uint32_t*)(smem + ((c & 1) ? S_B1 : S_B0));

#pragma unroll
            for (int k8 = 0; k8 < 4; k8++) {
                const int ko = k8 * 8;
                uint32_t a[4][4], b[4][2];
#pragma unroll
                for (int mt = 0; mt < 4; mt++) {
                    const int r0 = (wm * 64 + mt * 16 + ar) * KPAD + ko + ak;
                    a[mt][0] = As[r0];
                    a[mt][1] = As[r0 + 8 * KPAD];
                    a[mt][2] = As[r0 + 4];
                    a[mt][3] = As[r0 + 8 * KPAD + 4];
                }
#pragma unroll
                for (int nt = 0; nt < 4; nt++) {
                    const int nb = (wn * 32 + nt * 8 + ar) * KPAD + ko + ak;
                    b[nt][0] = Bs[nb];
                    b[nt][1] = Bs[nb + 4];
                }
#pragma unroll
                for (int mt = 0; mt < 4; mt++)
#pragma unroll
                    for (int nt = 0; nt < 4; nt++)
                        mma_tf32(acc[mt][nt], a[mt], b[nt]);
            }
            __syncthreads();
        }

        // ---- epilogue for this N pass: acc -> tanh -> v-dot row partials ----
#pragma unroll
        for (int mt = 0; mt < 4; mt++) {
#pragma unroll
            for (int nt = 0; nt < 4; nt++) {
                const int gn = p * N_TILE + wn * 32 + nt * 8 + 2 * ak;
                const float v0 = vs[gn], v1 = vs[gn + 1];
                const float t20 = t2s[gn], t21 = t2s[gn + 1];
                racc[mt * 2] += v0 * tanh_fast(acc[mt][nt][0] + t20)
                              + v1 * tanh_fast(acc[mt][nt][1] + t21);
                racc[mt * 2 + 1] += v0 * tanh_fast(acc[mt][nt][2] + t20)
                                  + v1 * tanh_fast(acc[mt][nt][3] + t21);
            }
        }
    }

    // reduce over the 4 lanes of each column group (ak bits of lane)
#pragma unroll
    for (int j = 0; j < 8; j++) {
        racc[j] += __shfl_xor_sync(0xFFFFFFFFu, racc[j], 1);
        racc[j] += __shfl_xor_sync(0xFFFFFFFFu, racc[j], 2);
    }
    if (ak == 0) {
#pragma unroll
        for (int j = 0; j < 8; j++) {
            const int row = wm * 64 + (j >> 1) * 16 + ar + (j & 1) * 8;
            atomicAdd(&part[row], racc[j]);
        }
    }
    __syncthreads();
    if (tid < M_TILE) out[m0 + tid] = part[tid];
}

// ---------------- launch ----------------
extern "C" void kernel_launch(void* const* d_in, const int* in_sizes, int n_in,
                              void* d_out, int out_size) {
    const float* X  = (const float*)d_in[0];   // inputs [B,S,D]
    const float* g  = (const float*)d_in[1];   // g [B,D]
    const float* WO = (const float*)d_in[2];   // WO [SIZE,D]
    const float* WG = (const float*)d_in[3];   // WG [SIZE,D]
    const float* v  = (const float*)d_in[4];   // v [1,SIZE]
    float* out = (float*)d_out;

    float* Xr;  cudaGetSymbolAddress((void**)&Xr,  g_Xr);
    float* WOr; cudaGetSymbolAddress((void**)&WOr, g_WOr);

    cudaFuncSetAttribute(fused_kernel, cudaFuncAttributeMaxDynamicSharedMemorySize, SMEM_BYTES);

    const int nX4 = BB * SEQ * DD / 4;
    round_kernel<<<nX4 / 256, 256>>>(X, Xr, nX4);
    const int nW4 = SZ * DD / 4;
    round_kernel<<<nW4 / 256, 256>>>(WO, WOr, nW4);
    term2_kernel<<<dim3(SZ / 8, BB), 256>>>(WG, g);

    fused_kernel<<<(BB * SEQ) / M_TILE, THREADS, SMEM_BYTES>>>(v, out);
}

// round 6
// speedup vs baseline: 1.0693x; 1.0540x over previous
#include <cuda_runtime.h>
#include <cstdint>
#include <cstddef>

#define DEV __device__ __forceinline__

// ---------------- problem constants ----------------
static constexpr int BB = 32;
static constexpr int SEQ = 2048;
static constexpr int DD = 1024;    // K
static constexpr int SZ = 1024;    // SIZE

static constexpr int M_TILE = 128;
static constexpr int N_TILE = 256;
static constexpr int PASSES = SZ / N_TILE;    // 4
static constexpr int K_CHUNK = 32;
static constexpr int NCHUNK = DD / K_CHUNK;   // 32
static constexpr int TOTAL_CHUNKS = PASSES * NCHUNK;   // 128
static constexpr int THREADS = 256;           // 8 warps: 2m x 4n, warp tile 64x64
static constexpr int KPAD = 36;               // floats per smem row (conflict-free)

// smem layout in floats: 3-stage ring of (A|B), then t2/v/part
static constexpr int A_FLOATS = M_TILE * KPAD;            // 4608
static constexpr int B_FLOATS = N_TILE * KPAD;            // 9216
static constexpr int STAGE_FLOATS = A_FLOATS + B_FLOATS;  // 13824
static constexpr int NSTAGE = 3;
static constexpr int S_T2 = NSTAGE * STAGE_FLOATS;        // 41472
static constexpr int S_V  = S_T2 + SZ;
static constexpr int S_PART = S_V + SZ;
static constexpr int SMEM_FLOATS = S_PART + M_TILE;
static constexpr int SMEM_BYTES = SMEM_FLOATS * 4;        // ~175 KB

// scratch: tf32-rounded copies + term2
__device__ float g_Xr[(size_t)BB * SEQ * DD];   // 256 MB
__device__ float g_WOr[(size_t)SZ * DD];        // 4 MB
__device__ float g_term2[BB * SZ];

// ---------------- helpers ----------------
DEV uint32_t smem_u32(const void* p) {
    uint32_t a;
    asm("{ .reg .u64 t; cvta.to.shared.u64 t, %1; cvt.u32.u64 %0, t; }" : "=r"(a) : "l"(p));
    return a;
}
DEV void cp16(uint32_t s, const void* g) {
    asm volatile("cp.async.cg.shared.global [%0], [%1], 16;" :: "r"(s), "l"(g));
}
DEV void cp_commit() { asm volatile("cp.async.commit_group;" ::: "memory"); }
template <int N> DEV void cp_wait() { asm volatile("cp.async.wait_group %0;" :: "n"(N) : "memory"); }

DEV float tanh_fast(float x) {
    float y;
    asm("tanh.approx.f32 %0, %1;" : "=f"(y) : "f"(x));
    return y;
}
DEV uint32_t rna_tf32(uint32_t b) {
    return (b + 0xFFFu + ((b >> 13) & 1u)) & 0xFFFFE000u;
}

DEV void mma_tf32(float* d, const uint32_t* a, const uint32_t* b) {
    asm volatile(
        "mma.sync.aligned.m16n8k8.row.col.f32.tf32.tf32.f32 "
        "{%0,%1,%2,%3}, {%4,%5,%6,%7}, {%8,%9}, {%0,%1,%2,%3};"
        : "+f"(d[0]), "+f"(d[1]), "+f"(d[2]), "+f"(d[3])
        : "r"(a[0]), "r"(a[1]), "r"(a[2]), "r"(a[3]), "r"(b[0]), "r"(b[1]));
}

// Stage chunk T (pass = T>>5, kc = T&31) into ring slot `slot`.
// A: [128 x 32] from Xr, B: [256 x 32] from WOr. 256 threads.
DEV void stage_T(float* smem, int slot, int T, const float* Xbase, int tid) {
    const int kc = T & (NCHUNK - 1);
    const int p = T >> 5;
    const float* asrc = Xbase + kc * K_CHUNK;
    const float* bsrc = g_WOr + (size_t)p * N_TILE * DD + kc * K_CHUNK;
    const uint32_t sa = smem_u32(smem + slot * STAGE_FLOATS);
    const uint32_t sbB = sa + A_FLOATS * 4;
#pragma unroll
    for (int it = 0; it < 4; it++) {   // A: 1024 xfers / 256 thr
        const int gidx = tid + it * THREADS;
        const int r = gidx >> 3, c = gidx & 7;
        cp16(sa + (uint32_t)(r * KPAD + c * 4) * 4u, asrc + (size_t)r * DD + c * 4);
    }
#pragma unroll
    for (int it = 0; it < 8; it++) {   // B: 2048 xfers / 256 thr
        const int gidx = tid + it * THREADS;
        const int r = gidx >> 3, c = gidx & 7;
        cp16(sbB + (uint32_t)(r * KPAD + c * 4) * 4u, bsrc + (size_t)r * DD + c * 4);
    }
}

// ---------------- prepass: tf32-rna rounding ----------------
__global__ void round_kernel(const float* __restrict__ src, float* __restrict__ dst, int n4) {
    int i = blockIdx.x * blockDim.x + threadIdx.x;
    if (i >= n4) return;
    uint4 u = ((const uint4*)src)[i];
    u.x = rna_tf32(u.x); u.y = rna_tf32(u.y); u.z = rna_tf32(u.z); u.w = rna_tf32(u.w);
    ((uint4*)dst)[i] = u;
}

// ---------------- term2 = WG @ g  (exact fp32 SIMT) ----------------
__global__ void term2_kernel(const float* __restrict__ WG, const float* __restrict__ g) {
    __shared__ float4 gs[256];
    const int b = blockIdx.y;
    gs[threadIdx.x] = ((const float4*)(g + (size_t)b * DD))[threadIdx.x];
    __syncthreads();
    const int w = threadIdx.x >> 5, l = threadIdx.x & 31;
    const int n = blockIdx.x * 8 + w;
    const float4* wg4 = (const float4*)(WG + (size_t)n * DD);
    float s = 0.f;
#pragma unroll
    for (int i = 0; i < 8; i++) {
        float4 a = wg4[l + 32 * i];
        float4 gg = gs[l + 32 * i];
        s += a.x * gg.x + a.y * gg.y + a.z * gg.z + a.w * gg.w;
    }
#pragma unroll
    for (int o = 16; o; o >>= 1) s += __shfl_xor_sync(0xFFFFFFFFu, s, o);
    if (l == 0) g_term2[b * SZ + n] = s;
}

// ---------------- fused GEMM(tf32 mma.sync) + tanh + v-dot ----------------
__global__ __launch_bounds__(THREADS, 1)
void fused_kernel(const float* __restrict__ v, float* __restrict__ out) {
    extern __shared__ float smem[];
    const int tid = threadIdx.x;
    const int lane = tid & 31, wid = tid >> 5;
    const int wm = wid >> 2, wn = wid & 3;      // 2 x 4 warp grid; warp tile 64x64
    const int m0 = blockIdx.x * M_TILE;
    const int bidx = m0 >> 11;                  // batch index

    float* t2s = smem + S_T2;
    float* vs  = smem + S_V;
    float* part = smem + S_PART;

    for (int i = tid; i < SZ; i += THREADS) {
        t2s[i] = g_term2[bidx * SZ + i];
        vs[i] = v[i];
    }
    for (int i = tid; i < M_TILE; i += THREADS) part[i] = 0.f;
    __syncthreads();

    const float* Xbase = g_Xr + (size_t)m0 * DD;

    float racc[8];
#pragma unroll
    for (int j = 0; j < 8; j++) racc[j] = 0.f;

    float acc[4][8][4];
#pragma unroll
    for (int mt = 0; mt < 4; mt++)
#pragma unroll
        for (int nt = 0; nt < 8; nt++)
#pragma unroll
            for (int q = 0; q < 4; q++) acc[mt][nt][q] = 0.f;

    const int ar = lane >> 2;   // fragment row
    const int ak = lane & 3;    // fragment k/col pair

    // prologue: prefetch chunks 0 and 1
    stage_T(smem, 0, 0, Xbase, tid);
    cp_commit();
    stage_T(smem, 1, 1, Xbase, tid);
    cp_commit();

    int bufR = 0;   // ring slot holding chunk T
    int bufS = 2;   // ring slot to stage chunk T+2 into

#pragma unroll 1
    for (int T = 0; T < TOTAL_CHUNKS; T++) {
        cp_wait<1>();        // chunk T's data resident (only T+1's group may pend)
        __syncthreads();     // all warps done with chunk T-1's buffer reads

        // prefetch chunk T+2 into the slot last read at chunk T-1 (drained above)
        if (T + 2 < TOTAL_CHUNKS) stage_T(smem, bufS, T + 2, Xbase, tid);
        cp_commit();         // always commit (possibly empty group) to keep counts aligned

        const uint32_t* As = (const uint32_t*)(smem + bufR * STAGE_FLOATS);
        const uint32_t* Bs = As + A_FLOATS;

#pragma unroll
        for (int k8 = 0; k8 < 4; k8++) {
            const int ko = k8 * 8;
            uint32_t a[4][4], b[8][2];
#pragma unroll
            for (int mt = 0; mt < 4; mt++) {
                const int r0 = (wm * 64 + mt * 16 + ar) * KPAD + ko + ak;
                a[mt][0] = As[r0];
                a[mt][1] = As[r0 + 8 * KPAD];
                a[mt][2] = As[r0 + 4];
                a[mt][3] = As[r0 + 8 * KPAD + 4];
            }
#pragma unroll
            for (int nt = 0; nt < 8; nt++) {
                const int nb = (wn * 64 + nt * 8 + ar) * KPAD + ko + ak;
                b[nt][0] = Bs[nb];
                b[nt][1] = Bs[nb + 4];
            }
#pragma unroll
            for (int mt = 0; mt < 4; mt++)
#pragma unroll
                for (int nt = 0; nt < 8; nt++)
                    mma_tf32(acc[mt][nt], a[mt], b[nt]);
        }

        // ---- pass boundary: epilogue (register-only + read-only smem; no barrier) ----
        if ((T & (NCHUNK - 1)) == NCHUNK - 1) {
            const int p = T >> 5;
#pragma unroll
            for (int mt = 0; mt < 4; mt++) {
#pragma unroll
                for (int nt = 0; nt < 8; nt++) {
                    const int gn = p * N_TILE + wn * 64 + nt * 8 + 2 * ak;
                    const float v0 = vs[gn], v1 = vs[gn + 1];
                    const float t20 = t2s[gn], t21 = t2s[gn + 1];
                    racc[mt * 2] += v0 * tanh_fast(acc[mt][nt][0] + t20)
                                  + v1 * tanh_fast(acc[mt][nt][1] + t21);
                    racc[mt * 2 + 1] += v0 * tanh_fast(acc[mt][nt][2] + t20)
                                      + v1 * tanh_fast(acc[mt][nt][3] + t21);
                    acc[mt][nt][0] = 0.f; acc[mt][nt][1] = 0.f;
                    acc[mt][nt][2] = 0.f; acc[mt][nt][3] = 0.f;
                }
            }
        }

        bufR = (bufR == 2) ? 0 : bufR + 1;
        bufS = (bufS == 2) ? 0 : bufS + 1;
    }

    // reduce over the 4 lanes of each column group
#pragma unroll
    for (int j = 0; j < 8; j++) {
        racc[j] += __shfl_xor_sync(0xFFFFFFFFu, racc[j], 1);
        racc[j] += __shfl_xor_sync(0xFFFFFFFFu, racc[j], 2);
    }
    if (ak == 0) {
#pragma unroll
        for (int j = 0; j < 8; j++) {
            const int row = wm * 64 + (j >> 1) * 16 + ar + (j & 1) * 8;
            atomicAdd(&part[row], racc[j]);
        }
    }
    __syncthreads();
    if (tid < M_TILE) out[m0 + tid] = part[tid];
}

// ---------------- launch ----------------
extern "C" void kernel_launch(void* const* d_in, const int* in_sizes, int n_in,
                              void* d_out, int out_size) {
    const float* X  = (const float*)d_in[0];   // inputs [B,S,D]
    const float* g  = (const float*)d_in[1];   // g [B,D]
    const float* WO = (const float*)d_in[2];   // WO [SIZE,D]
    const float* WG = (const float*)d_in[3];   // WG [SIZE,D]
    const float* v  = (const float*)d_in[4];   // v [1,SIZE]
    float* out = (float*)d_out;

    float* Xr;  cudaGetSymbolAddress((void**)&Xr,  g_Xr);
    float* WOr; cudaGetSymbolAddress((void**)&WOr, g_WOr);

    cudaFuncSetAttribute(fused_kernel, cudaFuncAttributeMaxDynamicSharedMemorySize, SMEM_BYTES);

    const int nX4 = BB * SEQ * DD / 4;
    round_kernel<<<nX4 / 256, 256>>>(X, Xr, nX4);
    const int nW4 = SZ * DD / 4;
    round_kernel<<<nW4 / 256, 256>>>(WO, WOr, nW4);
    term2_kernel<<<dim3(SZ / 8, BB), 256>>>(WG, g);

    fused_kernel<<<(BB * SEQ) / M_TILE, THREADS, SMEM_BYTES>>>(v, out);
}

// round 7
// speedup vs baseline: 1.7092x; 1.5985x over previous
#include <cuda_runtime.h>
#include <cuda_fp16.h>
#include <cstdint>
#include <cstddef>

#define DEV __device__ __forceinline__

// ---------------- problem constants ----------------
static constexpr int BB = 32;
static constexpr int SEQ = 2048;
static constexpr int DD = 1024;    // K
static constexpr int SZ = 1024;    // SIZE

static constexpr int M_TILE = 128;
static constexpr int N_TILE = 256;
static constexpr int PASSES = SZ / N_TILE;    // 4
static constexpr int K_CHUNK = 32;            // k elems per chunk
static constexpr int NCHUNK = DD / K_CHUNK;   // 32
static constexpr int TOTAL_CHUNKS = PASSES * NCHUNK;   // 128
static constexpr int THREADS = 256;           // 8 warps: 2m x 4n, warp tile 64x64
static constexpr int KPH = 40;                // halves per smem row (80 B; conflict-free)

// smem ring: 3 stages of (A|B) in halves, then t2/v/part in floats
static constexpr int A_HALVES = M_TILE * KPH;             // 5120
static constexpr int B_HALVES = N_TILE * KPH;             // 10240
static constexpr int STAGE_HALVES = A_HALVES + B_HALVES;  // 15360
static constexpr int NSTAGE = 3;
static constexpr int RING_BYTES = NSTAGE * STAGE_HALVES * 2;       // 92160
static constexpr int SMEM_BYTES = RING_BYTES + (SZ + SZ + M_TILE) * 4;  // ~100.9 KB

// scratch: fp16 copies + term2
__device__ __half g_Xh[(size_t)BB * SEQ * DD];   // 128 MB
__device__ __half g_WOh[(size_t)SZ * DD];        // 2 MB
__device__ float g_term2[BB * SZ];

// ---------------- helpers ----------------
DEV uint32_t smem_u32(const void* p) {
    uint32_t a;
    asm("{ .reg .u64 t; cvta.to.shared.u64 t, %1; cvt.u32.u64 %0, t; }" : "=r"(a) : "l"(p));
    return a;
}
DEV void cp16(uint32_t s, const void* g) {
    asm volatile("cp.async.cg.shared.global [%0], [%1], 16;" :: "r"(s), "l"(g));
}
DEV void cp_commit() { asm volatile("cp.async.commit_group;" ::: "memory"); }
template <int N> DEV void cp_wait() { asm volatile("cp.async.wait_group %0;" :: "n"(N) : "memory"); }

DEV float tanh_fast(float x) {
    float y;
    asm("tanh.approx.f32 %0, %1;" : "=f"(y) : "f"(x));
    return y;
}

DEV void mma_f16(float* d, const uint32_t* a, const uint32_t* b) {
    asm volatile(
        "mma.sync.aligned.m16n8k16.row.col.f32.f16.f16.f32 "
        "{%0,%1,%2,%3}, {%4,%5,%6,%7}, {%8,%9}, {%0,%1,%2,%3};"
        : "+f"(d[0]), "+f"(d[1]), "+f"(d[2]), "+f"(d[3])
        : "r"(a[0]), "r"(a[1]), "r"(a[2]), "r"(a[3]), "r"(b[0]), "r"(b[1]));
}

// Stage chunk T (pass = T>>5, kc = T&31) into ring slot `slot` (fp16 data).
// A: [128 x 32h] = 512 xfers, B: [256 x 32h] = 1024 xfers; 256 threads.
DEV void stage_T(char* smem, int slot, int T, const __half* Xbase, int tid) {
    const int kc = T & (NCHUNK - 1);
    const int p = T >> 5;
    const __half* asrc = Xbase + kc * K_CHUNK;
    const __half* bsrc = g_WOh + (size_t)p * N_TILE * DD + kc * K_CHUNK;
    const uint32_t sa = smem_u32(smem) + (uint32_t)slot * STAGE_HALVES * 2u;
    const uint32_t sbB = sa + A_HALVES * 2u;
#pragma unroll
    for (int it = 0; it < 2; it++) {   // A: 512 xfers (4 per row)
        const int gidx = tid + it * THREADS;
        const int r = gidx >> 2, c = gidx & 3;
        cp16(sa + (uint32_t)(r * KPH * 2 + c * 16), asrc + (size_t)r * DD + c * 8);
    }
#pragma unroll
    for (int it = 0; it < 4; it++) {   // B: 1024 xfers
        const int gidx = tid + it * THREADS;
        const int r = gidx >> 2, c = gidx & 3;
        cp16(sbB + (uint32_t)(r * KPH * 2 + c * 16), bsrc + (size_t)r * DD + c * 8);
    }
}

// ---------------- prepass: fp32 -> fp16 (rn) ----------------
__global__ void tohalf_kernel(const float* __restrict__ src, uint2* __restrict__ dst, int n4) {
    int i = blockIdx.x * blockDim.x + threadIdx.x;
    if (i >= n4) return;
    float4 u = ((const float4*)src)[i];
    __half2 h0 = __floats2half2_rn(u.x, u.y);
    __half2 h1 = __floats2half2_rn(u.z, u.w);
    uint2 o;
    o.x = *(uint32_t*)&h0;
    o.y = *(uint32_t*)&h1;
    dst[i] = o;
}

// ---------------- term2 = WG @ g  (exact fp32 SIMT) ----------------
__global__ void term2_kernel(const float* __restrict__ WG, const float* __restrict__ g) {
    __shared__ float4 gs[256];
    const int b = blockIdx.y;
    gs[threadIdx.x] = ((const float4*)(g + (size_t)b * DD))[threadIdx.x];
    __syncthreads();
    const int w = threadIdx.x >> 5, l = threadIdx.x & 31;
    const int n = blockIdx.x * 8 + w;
    const float4* wg4 = (const float4*)(WG + (size_t)n * DD);
    float s = 0.f;
#pragma unroll
    for (int i = 0; i < 8; i++) {
        float4 a = wg4[l + 32 * i];
        float4 gg = gs[l + 32 * i];
        s += a.x * gg.x + a.y * gg.y + a.z * gg.z + a.w * gg.w;
    }
#pragma unroll
    for (int o = 16; o; o >>= 1) s += __shfl_xor_sync(0xFFFFFFFFu, s, o);
    if (l == 0) g_term2[b * SZ + n] = s;
}

// ---------------- fused GEMM(fp16 mma.sync) + tanh + v-dot ----------------
__global__ __launch_bounds__(THREADS, 1)
void fused_kernel(const float* __restrict__ v, float* __restrict__ out) {
    extern __shared__ char smem[];
    const int tid = threadIdx.x;
    const int lane = tid & 31, wid = tid >> 5;
    const int wm = wid >> 2, wn = wid & 3;      // 2 x 4 warp grid; warp tile 64x64
    const int m0 = blockIdx.x * M_TILE;
    const int bidx = m0 >> 11;                  // batch index

    float* t2s = (float*)(smem + RING_BYTES);
    float* vs = t2s + SZ;
    float* part = vs + SZ;

    for (int i = tid; i < SZ; i += THREADS) {
        t2s[i] = g_term2[bidx * SZ + i];
        vs[i] = v[i];
    }
    for (int i = tid; i < M_TILE; i += THREADS) part[i] = 0.f;
    __syncthreads();

    const __half* Xbase = g_Xh + (size_t)m0 * DD;

    float racc[8];
#pragma unroll
    for (int j = 0; j < 8; j++) racc[j] = 0.f;

    float acc[4][8][4];
#pragma unroll
    for (int mt = 0; mt < 4; mt++)
#pragma unroll
        for (int nt = 0; nt < 8; nt++)
#pragma unroll
            for (int q = 0; q < 4; q++) acc[mt][nt][q] = 0.f;

    const int ar = lane >> 2;   // fragment row
    const int ak = lane & 3;    // fragment k-pair

    // prologue: prefetch chunks 0 and 1
    stage_T(smem, 0, 0, Xbase, tid);
    cp_commit();
    stage_T(smem, 1, 1, Xbase, tid);
    cp_commit();

    int bufR = 0;   // ring slot holding chunk T
    int bufS = 2;   // ring slot to stage chunk T+2 into

#pragma unroll 1
    for (int T = 0; T < TOTAL_CHUNKS; T++) {
        cp_wait<1>();        // chunk T resident (only T+1's group may pend)
        __syncthreads();     // all warps done reading the slot we're about to fill

        if (T + 2 < TOTAL_CHUNKS) stage_T(smem, bufS, T + 2, Xbase, tid);
        cp_commit();         // keep group counts aligned

        // u32 views of this stage's A and B (2 halves per u32; row = KPH/2=20 u32)
        const uint32_t* As = (const uint32_t*)(smem + (size_t)bufR * STAGE_HALVES * 2);
        const uint32_t* Bs = As + A_HALVES / 2;

#pragma unroll
        for (int k16 = 0; k16 < 2; k16++) {     // two m16n8k16 steps cover 32 k
            const int ko = k16 * 8;             // u32 offset within row
            uint32_t a[4][4], b[8][2];
#pragma unroll
            for (int mt = 0; mt < 4; mt++) {
                const int r0 = (wm * 64 + mt * 16 + ar) * (KPH / 2) + ko + ak;
                a[mt][0] = As[r0];                       // k 0-7 halves pair
                a[mt][1] = As[r0 + 8 * (KPH / 2)];       // row+8
                a[mt][2] = As[r0 + 4];                   // k 8-15
                a[mt][3] = As[r0 + 8 * (KPH / 2) + 4];
            }
#pragma unroll
            for (int nt = 0; nt < 8; nt++) {
                const int nb = (wn * 64 + nt * 8 + ar) * (KPH / 2) + ko + ak;
                b[nt][0] = Bs[nb];
                b[nt][1] = Bs[nb + 4];
            }
#pragma unroll
            for (int mt = 0; mt < 4; mt++)
#pragma unroll
                for (int nt = 0; nt < 8; nt++)
                    mma_f16(acc[mt][nt], a[mt], b[nt]);
        }

        // ---- pass boundary: epilogue (register-only + read-only smem; no barrier) ----
        if ((T & (NCHUNK - 1)) == NCHUNK - 1) {
            const int p = T >> 5;
#pragma unroll
            for (int mt = 0; mt < 4; mt++) {
#pragma unroll
                for (int nt = 0; nt < 8; nt++) {
                    const int gn = p * N_TILE + wn * 64 + nt * 8 + 2 * ak;
                    const float v0 = vs[gn], v1 = vs[gn + 1];
                    const float t20 = t2s[gn], t21 = t2s[gn + 1];
                    racc[mt * 2] += v0 * tanh_fast(acc[mt][nt][0] + t20)
                                  + v1 * tanh_fast(acc[mt][nt][1] + t21);
                    racc[mt * 2 + 1] += v0 * tanh_fast(acc[mt][nt][2] + t20)
                                      + v1 * tanh_fast(acc[mt][nt][3] + t21);
                    acc[mt][nt][0] = 0.f; acc[mt][nt][1] = 0.f;
                    acc[mt][nt][2] = 0.f; acc[mt][nt][3] = 0.f;
                }
            }
        }

        bufR = (bufR == 2) ? 0 : bufR + 1;
        bufS = (bufS == 2) ? 0 : bufS + 1;
    }

    // reduce over the 4 lanes of each column group
#pragma unroll
    for (int j = 0; j < 8; j++) {
        racc[j] += __shfl_xor_sync(0xFFFFFFFFu, racc[j], 1);
        racc[j] += __shfl_xor_sync(0xFFFFFFFFu, racc[j], 2);
    }
    if (ak == 0) {
#pragma unroll
        for (int j = 0; j < 8; j++) {
            const int row = wm * 64 + (j >> 1) * 16 + ar + (j & 1) * 8;
            atomicAdd(&part[row], racc[j]);
        }
    }
    __syncthreads();
    if (tid < M_TILE) out[m0 + tid] = part[tid];
}

// ---------------- launch ----------------
extern "C" void kernel_launch(void* const* d_in, const int* in_sizes, int n_in,
                              void* d_out, int out_size) {
    const float* X  = (const float*)d_in[0];   // inputs [B,S,D]
    const float* g  = (const float*)d_in[1];   // g [B,D]
    const float* WO = (const float*)d_in[2];   // WO [SIZE,D]
    const float* WG = (const float*)d_in[3];   // WG [SIZE,D]
    const float* v  = (const float*)d_in[4];   // v [1,SIZE]
    float* out = (float*)d_out;

    __half* Xh;  cudaGetSymbolAddress((void**)&Xh,  g_Xh);
    __half* WOh; cudaGetSymbolAddress((void**)&WOh, g_WOh);

    cudaFuncSetAttribute(fused_kernel, cudaFuncAttributeMaxDynamicSharedMemorySize, SMEM_BYTES);

    const int nX4 = BB * SEQ * DD / 4;
    tohalf_kernel<<<nX4 / 256, 256>>>(X, (uint2*)Xh, nX4);
    const int nW4 = SZ * DD / 4;
    tohalf_kernel<<<nW4 / 256, 256>>>(WO, (uint2*)WOh, nW4);
    term2_kernel<<<dim3(SZ / 8, BB), 256>>>(WG, g);

    fused_kernel<<<(BB * SEQ) / M_TILE, THREADS, SMEM_BYTES>>>(v, out);
}

// round 8
// speedup vs baseline: 1.9254x; 1.1265x over previous
#include <cuda_runtime.h>
#include <cuda_fp16.h>
#include <cstdint>
#include <cstddef>

#define DEV __device__ __forceinline__

// ---------------- problem constants ----------------
static constexpr int BB = 32;
static constexpr int SEQ = 2048;
static constexpr int DD = 1024;    // K
static constexpr int SZ = 1024;    // SIZE

static constexpr int M_TILE = 128;
static constexpr int N_TILE = 128;            // halved: 2 CTAs/SM for phase diversity
static constexpr int PASSES = SZ / N_TILE;    // 8
static constexpr int K_CHUNK = 32;
static constexpr int NCHUNK = DD / K_CHUNK;   // 32
static constexpr int TOTAL_CHUNKS = PASSES * NCHUNK;   // 256
static constexpr int THREADS = 128;           // 4 warps: 2m x 2n, warp tile 64x64
static constexpr int KPH = 40;                // halves per smem row (80 B; conflict-free)

// smem ring: 3 stages of (A|B) in halves, then t2/v/part in floats
static constexpr int A_HALVES = M_TILE * KPH;             // 5120
static constexpr int B_HALVES = N_TILE * KPH;             // 5120
static constexpr int STAGE_HALVES = A_HALVES + B_HALVES;  // 10240
static constexpr int NSTAGE = 3;
static constexpr int RING_BYTES = NSTAGE * STAGE_HALVES * 2;            // 61440
static constexpr int SMEM_BYTES = RING_BYTES + (SZ + SZ + M_TILE) * 4;  // ~69.5 KB -> 2 CTAs/SM

// scratch: fp16 copies + term2
__device__ __half g_Xh[(size_t)BB * SEQ * DD];   // 128 MB
__device__ __half g_WOh[(size_t)SZ * DD];        // 2 MB
__device__ float g_term2[BB * SZ];

// ---------------- helpers ----------------
DEV uint32_t smem_u32(const void* p) {
    uint32_t a;
    asm("{ .reg .u64 t; cvta.to.shared.u64 t, %1; cvt.u32.u64 %0, t; }" : "=r"(a) : "l"(p));
    return a;
}
DEV void cp16(uint32_t s, const void* g) {
    asm volatile("cp.async.cg.shared.global [%0], [%1], 16;" :: "r"(s), "l"(g));
}
DEV void cp_commit() { asm volatile("cp.async.commit_group;" ::: "memory"); }
template <int N> DEV void cp_wait() { asm volatile("cp.async.wait_group %0;" :: "n"(N) : "memory"); }

DEV float tanh_fast(float x) {
    float y;
    asm("tanh.approx.f32 %0, %1;" : "=f"(y) : "f"(x));
    return y;
}

DEV void mma_f16(float* d, const uint32_t* a, const uint32_t* b) {
    asm volatile(
        "mma.sync.aligned.m16n8k16.row.col.f32.f16.f16.f32 "
        "{%0,%1,%2,%3}, {%4,%5,%6,%7}, {%8,%9}, {%0,%1,%2,%3};"
        : "+f"(d[0]), "+f"(d[1]), "+f"(d[2]), "+f"(d[3])
        : "r"(a[0]), "r"(a[1]), "r"(a[2]), "r"(a[3]), "r"(b[0]), "r"(b[1]));
}

// Stage chunk T (pass = T/NCHUNK, kc = T%NCHUNK) into ring slot `slot`.
// A: [128 x 32h] = 512 xfers, B: [128 x 32h] = 512 xfers; 128 threads -> 4+4 iters.
DEV void stage_T(char* smem, int slot, int T, const __half* Xbase, int tid) {
    const int kc = T & (NCHUNK - 1);
    const int p = T >> 5;
    const __half* asrc = Xbase + kc * K_CHUNK;
    const __half* bsrc = g_WOh + (size_t)p * N_TILE * DD + kc * K_CHUNK;
    const uint32_t sa = smem_u32(smem) + (uint32_t)slot * STAGE_HALVES * 2u;
    const uint32_t sbB = sa + A_HALVES * 2u;
#pragma unroll
    for (int it = 0; it < 4; it++) {   // A
        const int gidx = tid + it * THREADS;
        const int r = gidx >> 2, c = gidx & 3;
        cp16(sa + (uint32_t)(r * KPH * 2 + c * 16), asrc + (size_t)r * DD + c * 8);
    }
#pragma unroll
    for (int it = 0; it < 4; it++) {   // B
        const int gidx = tid + it * THREADS;
        const int r = gidx >> 2, c = gidx & 3;
        cp16(sbB + (uint32_t)(r * KPH * 2 + c * 16), bsrc + (size_t)r * DD + c * 8);
    }
}

// ---------------- prepass: fp32 -> fp16 (rn) ----------------
__global__ void tohalf_kernel(const float* __restrict__ src, uint2* __restrict__ dst, int n4) {
    int i = blockIdx.x * blockDim.x + threadIdx.x;
    if (i >= n4) return;
    float4 u = ((const float4*)src)[i];
    __half2 h0 = __floats2half2_rn(u.x, u.y);
    __half2 h1 = __floats2half2_rn(u.z, u.w);
    uint2 o;
    o.x = *(uint32_t*)&h0;
    o.y = *(uint32_t*)&h1;
    dst[i] = o;
}

// ---------------- term2 = WG @ g  (exact fp32 SIMT) ----------------
__global__ void term2_kernel(const float* __restrict__ WG, const float* __restrict__ g) {
    __shared__ float4 gs[256];
    const int b = blockIdx.y;
    gs[threadIdx.x] = ((const float4*)(g + (size_t)b * DD))[threadIdx.x];
    __syncthreads();
    const int w = threadIdx.x >> 5, l = threadIdx.x & 31;
    const int n = blockIdx.x * 8 + w;
    const float4* wg4 = (const float4*)(WG + (size_t)n * DD);
    float s = 0.f;
#pragma unroll
    for (int i = 0; i < 8; i++) {
        float4 a = wg4[l + 32 * i];
        float4 gg = gs[l + 32 * i];
        s += a.x * gg.x + a.y * gg.y + a.z * gg.z + a.w * gg.w;
    }
#pragma unroll
    for (int o = 16; o; o >>= 1) s += __shfl_xor_sync(0xFFFFFFFFu, s, o);
    if (l == 0) g_term2[b * SZ + n] = s;
}

// ---------------- fused GEMM(fp16 mma.sync) + tanh + v-dot ----------------
__global__ __launch_bounds__(THREADS, 2)
void fused_kernel(const float* __restrict__ v, float* __restrict__ out) {
    extern __shared__ char smem[];
    const int tid = threadIdx.x;
    const int lane = tid & 31, wid = tid >> 5;
    const int wm = wid >> 1, wn = wid & 1;      // 2 x 2 warp grid; warp tile 64x64
    const int m0 = blockIdx.x * M_TILE;
    const int bidx = m0 >> 11;                  // batch index

    float* t2s = (float*)(smem + RING_BYTES);
    float* vs = t2s + SZ;
    float* part = vs + SZ;

    for (int i = tid; i < SZ; i += THREADS) {
        t2s[i] = g_term2[bidx * SZ + i];
        vs[i] = v[i];
    }
    for (int i = tid; i < M_TILE; i += THREADS) part[i] = 0.f;
    __syncthreads();

    const __half* Xbase = g_Xh + (size_t)m0 * DD;

    float racc[8];
#pragma unroll
    for (int j = 0; j < 8; j++) racc[j] = 0.f;

    float acc[4][8][4];
#pragma unroll
    for (int mt = 0; mt < 4; mt++)
#pragma unroll
        for (int nt = 0; nt < 8; nt++)
#pragma unroll
            for (int q = 0; q < 4; q++) acc[mt][nt][q] = 0.f;

    const int ar = lane >> 2;   // fragment row
    const int ak = lane & 3;    // fragment k-pair

    // prologue: prefetch chunks 0 and 1
    stage_T(smem, 0, 0, Xbase, tid);
    cp_commit();
    stage_T(smem, 1, 1, Xbase, tid);
    cp_commit();

    int bufR = 0;   // ring slot holding chunk T
    int bufS = 2;   // ring slot to stage chunk T+2 into

#pragma unroll 1
    for (int T = 0; T < TOTAL_CHUNKS; T++) {
        cp_wait<1>();        // chunk T resident (only T+1's group may pend)
        __syncthreads();     // all warps done reading the slot we're about to fill

        if (T + 2 < TOTAL_CHUNKS) stage_T(smem, bufS, T + 2, Xbase, tid);
        cp_commit();         // keep group counts aligned

        const uint32_t* As = (const uint32_t*)(smem + (size_t)bufR * STAGE_HALVES * 2);
        const uint32_t* Bs = As + A_HALVES / 2;

#pragma unroll
        for (int k16 = 0; k16 < 2; k16++) {     // two m16n8k16 steps cover 32 k
            const int ko = k16 * 8;             // u32 offset within row
            uint32_t a[4][4], b[8][2];
#pragma unroll
            for (int mt = 0; mt < 4; mt++) {
                const int r0 = (wm * 64 + mt * 16 + ar) * (KPH / 2) + ko + ak;
                a[mt][0] = As[r0];
                a[mt][1] = As[r0 + 8 * (KPH / 2)];
                a[mt][2] = As[r0 + 4];
                a[mt][3] = As[r0 + 8 * (KPH / 2) + 4];
            }
#pragma unroll
            for (int nt = 0; nt < 8; nt++) {
                const int nb = (wn * 64 + nt * 8 + ar) * (KPH / 2) + ko + ak;
                b[nt][0] = Bs[nb];
                b[nt][1] = Bs[nb + 4];
            }
#pragma unroll
            for (int mt = 0; mt < 4; mt++)
#pragma unroll
                for (int nt = 0; nt < 8; nt++)
                    mma_f16(acc[mt][nt], a[mt], b[nt]);
        }

        // ---- pass boundary: epilogue (register-only + read-only smem; no barrier) ----
        if ((T & (NCHUNK - 1)) == NCHUNK - 1) {
            const int p = T >> 5;
#pragma unroll
            for (int mt = 0; mt < 4; mt++) {
#pragma unroll
                for (int nt = 0; nt < 8; nt++) {
                    const int gn = p * N_TILE + wn * 64 + nt * 8 + 2 * ak;
                    const float v0 = vs[gn], v1 = vs[gn + 1];
                    const float t20 = t2s[gn], t21 = t2s[gn + 1];
                    racc[mt * 2] += v0 * tanh_fast(acc[mt][nt][0] + t20)
                                  + v1 * tanh_fast(acc[mt][nt][1] + t21);
                    racc[mt * 2 + 1] += v0 * tanh_fast(acc[mt][nt][2] + t20)
                                      + v1 * tanh_fast(acc[mt][nt][3] + t21);
                    acc[mt][nt][0] = 0.f; acc[mt][nt][1] = 0.f;
                    acc[mt][nt][2] = 0.f; acc[mt][nt][3] = 0.f;
                }
            }
        }

        bufR = (bufR == 2) ? 0 : bufR + 1;
        bufS = (bufS == 2) ? 0 : bufS + 1;
    }

    // reduce over the 4 lanes of each column group
#pragma unroll
    for (int j = 0; j < 8; j++) {
        racc[j] += __shfl_xor_sync(0xFFFFFFFFu, racc[j], 1);
        racc[j] += __shfl_xor_sync(0xFFFFFFFFu, racc[j], 2);
    }
    if (ak == 0) {
#pragma unroll
        for (int j = 0; j < 8; j++) {
            const int row = wm * 64 + (j >> 1) * 16 + ar + (j & 1) * 8;
            atomicAdd(&part[row], racc[j]);
        }
    }
    __syncthreads();
    if (tid < M_TILE) out[m0 + tid] = part[tid];
}

// ---------------- launch ----------------
extern "C" void kernel_launch(void* const* d_in, const int* in_sizes, int n_in,
                              void* d_out, int out_size) {
    const float* X  = (const float*)d_in[0];   // inputs [B,S,D]
    const float* g  = (const float*)d_in[1];   // g [B,D]
    const float* WO = (const float*)d_in[2];   // WO [SIZE,D]
    const float* WG = (const float*)d_in[3];   // WG [SIZE,D]
    const float* v  = (const float*)d_in[4];   // v [1,SIZE]
    float* out = (float*)d_out;

    __half* Xh;  cudaGetSymbolAddress((void**)&Xh,  g_Xh);
    __half* WOh; cudaGetSymbolAddress((void**)&WOh, g_WOh);

    cudaFuncSetAttribute(fused_kernel, cudaFuncAttributeMaxDynamicSharedMemorySize, SMEM_BYTES);

    const int nX4 = BB * SEQ * DD / 4;
    tohalf_kernel<<<nX4 / 256, 256>>>(X, (uint2*)Xh, nX4);
    const int nW4 = SZ * DD / 4;
    tohalf_kernel<<<nW4 / 256, 256>>>(WO, (uint2*)WOh, nW4);
    term2_kernel<<<dim3(SZ / 8, BB), 256>>>(WG, g);

    fused_kernel<<<(BB * SEQ) / M_TILE, THREADS, SMEM_BYTES>>>(v, out);
}

// round 10
// speedup vs baseline: 2.0295x; 1.0541x over previous
#include <cuda_runtime.h>
#include <cuda_fp16.h>
#include <cstdint>
#include <cstddef>

#define DEV __device__ __forceinline__

// ---------------- problem constants ----------------
static constexpr int BB = 32;
static constexpr int SEQ = 2048;
static constexpr int DD = 1024;    // K
static constexpr int SZ = 1024;    // SIZE

static constexpr int M_TILE = 128;
static constexpr int N_TILE = 128;            // 2 CTAs/SM for phase diversity
static constexpr int PASSES = SZ / N_TILE;    // 8
static constexpr int K_CHUNK = 64;            // halves of K per chunk
static constexpr int NCHUNK = DD / K_CHUNK;   // 16
static constexpr int TOTAL_CHUNKS = PASSES * NCHUNK;   // 128
static constexpr int THREADS = 128;           // 4 warps: 2m x 2n, warp tile 64x64
static constexpr int KPH = 72;                // halves per smem row (144 B; 4ar+ak conflict-free)

// smem: 3-stage ring of (A|B) halves + 128-float partial buffer
static constexpr int A_HALVES = M_TILE * KPH;             // 9216
static constexpr int B_HALVES = N_TILE * KPH;             // 9216
static constexpr int STAGE_HALVES = A_HALVES + B_HALVES;  // 18432
static constexpr int NSTAGE = 3;
static constexpr int RING_BYTES = NSTAGE * STAGE_HALVES * 2;   // 110592
static constexpr int SMEM_BYTES = RING_BYTES + M_TILE * 4;     // 111104 -> 2 CTAs/SM

// scratch: fp16 copies + packed (v, term2) table
__device__ __half g_Xh[(size_t)BB * SEQ * DD];   // 128 MB
__device__ __half g_WOh[(size_t)SZ * DD];        // 2 MB
__device__ float2 g_vt2[BB * SZ];                // {v[n], term2[b][n]}

// ---------------- helpers ----------------
DEV uint32_t smem_u32(const void* p) {
    uint32_t a;
    asm("{ .reg .u64 t; cvta.to.shared.u64 t, %1; cvt.u32.u64 %0, t; }" : "=r"(a) : "l"(p));
    return a;
}
DEV void cp16(uint32_t s, const void* g) {
    asm volatile("cp.async.cg.shared.global [%0], [%1], 16;" :: "r"(s), "l"(g));
}
DEV void cp_commit() { asm volatile("cp.async.commit_group;" ::: "memory"); }
template <int N> DEV void cp_wait() { asm volatile("cp.async.wait_group %0;" :: "n"(N) : "memory"); }

DEV float tanh_fast(float x) {
    float y;
    asm("tanh.approx.f32 %0, %1;" : "=f"(y) : "f"(x));
    return y;
}

DEV void mma_f16(float* d, const uint32_t* a, const uint32_t* b) {
    asm volatile(
        "mma.sync.aligned.m16n8k16.row.col.f32.f16.f16.f32 "
        "{%0,%1,%2,%3}, {%4,%5,%6,%7}, {%8,%9}, {%0,%1,%2,%3};"
        : "+f"(d[0]), "+f"(d[1]), "+f"(d[2]), "+f"(d[3])
        : "r"(a[0]), "r"(a[1]), "r"(a[2]), "r"(a[3]), "r"(b[0]), "r"(b[1]));
}

// Stage chunk T (pass = T/16, kc = T%16) into ring slot `slot`.
// A: [128 x 64h] = 1024 cp16, B: [128 x 64h] = 1024 cp16; 128 threads.
DEV void stage_T(char* smem, int slot, int T, const __half* Xbase, int tid) {
    const int kc = T & (NCHUNK - 1);
    const int p = T >> 4;
    const __half* asrc = Xbase + kc * K_CHUNK;
    const __half* bsrc = g_WOh + (size_t)p * N_TILE * DD + kc * K_CHUNK;
    const uint32_t sa = smem_u32(smem) + (uint32_t)slot * STAGE_HALVES * 2u;
    const uint32_t sbB = sa + A_HALVES * 2u;
#pragma unroll
    for (int it = 0; it < 8; it++) {   // A
        const int gidx = tid + it * THREADS;
        const int r = gidx >> 3, c = gidx & 7;
        cp16(sa + (uint32_t)(r * KPH * 2 + c * 16), asrc + (size_t)r * DD + c * 8);
    }
#pragma unroll
    for (int it = 0; it < 8; it++) {   // B
        const int gidx = tid + it * THREADS;
        const int r = gidx >> 3, c = gidx & 7;
        cp16(sbB + (uint32_t)(r * KPH * 2 + c * 16), bsrc + (size_t)r * DD + c * 8);
    }
}

// ---------------- prepass: fp32 -> fp16 (rn) ----------------
__global__ void tohalf_kernel(const float* __restrict__ src, uint2* __restrict__ dst, int n4) {
    int i = blockIdx.x * blockDim.x + threadIdx.x;
    if (i >= n4) return;
    float4 u = ((const float4*)src)[i];
    __half2 h0 = __floats2half2_rn(u.x, u.y);
    __half2 h1 = __floats2half2_rn(u.z, u.w);
    uint2 o;
    o.x = *(uint32_t*)&h0;
    o.y = *(uint32_t*)&h1;
    dst[i] = o;
}

// ---------------- term2 = WG @ g, packed with v ----------------
__global__ void term2_kernel(const float* __restrict__ WG, const float* __restrict__ g,
                             const float* __restrict__ v) {
    __shared__ float4 gs[256];
    const int b = blockIdx.y;
    gs[threadIdx.x] = ((const float4*)(g + (size_t)b * DD))[threadIdx.x];
    __syncthreads();
    const int w = threadIdx.x >> 5, l = threadIdx.x & 31;
    const int n = blockIdx.x * 8 + w;
    const float4* wg4 = (const float4*)(WG + (size_t)n * DD);
    float s = 0.f;
#pragma unroll
    for (int i = 0; i < 8; i++) {
        float4 a = wg4[l + 32 * i];
        float4 gg = gs[l + 32 * i];
        s += a.x * gg.x + a.y * gg.y + a.z * gg.z + a.w * gg.w;
    }
#pragma unroll
    for (int o = 16; o; o >>= 1) s += __shfl_xor_sync(0xFFFFFFFFu, s, o);
    if (l == 0) g_vt2[b * SZ + n] = make_float2(v[n], s);
}

// ---------------- fused GEMM(fp16 mma.sync) + tanh + v-dot ----------------
__global__ __launch_bounds__(THREADS, 2)
void fused_kernel(float* __restrict__ out) {
    extern __shared__ char smem[];
    const int tid = threadIdx.x;
    const int lane = tid & 31, wid = tid >> 5;
    const int wm = wid >> 1, wn = wid & 1;      // 2 x 2 warp grid; warp tile 64x64
    const int m0 = blockIdx.x * M_TILE;
    const int bidx = m0 >> 11;                  // batch index

    float* part = (float*)(smem + RING_BYTES);
    for (int i = tid; i < M_TILE; i += THREADS) part[i] = 0.f;

    const __half* Xbase = g_Xh + (size_t)m0 * DD;
    const float4* vt4 = (const float4*)(g_vt2 + (size_t)bidx * SZ);   // 2 cols per float4

    float racc[8];
#pragma unroll
    for (int j = 0; j < 8; j++) racc[j] = 0.f;

    float acc[4][8][4];
#pragma unroll
    for (int mt = 0; mt < 4; mt++)
#pragma unroll
        for (int nt = 0; nt < 8; nt++)
#pragma unroll
            for (int q = 0; q < 4; q++) acc[mt][nt][q] = 0.f;

    const int ar = lane >> 2;   // fragment row
    const int ak = lane & 3;    // fragment k-pair

    // prologue: prefetch chunks 0 and 1
    stage_T(smem, 0, 0, Xbase, tid);
    cp_commit();
    stage_T(smem, 1, 1, Xbase, tid);
    cp_commit();

    int bufR = 0;   // slot holding chunk T
    int bufS = 2;   // slot to stage chunk T+2 into (read at T-1, drained by barrier)

#pragma unroll 1
    for (int T = 0; T < TOTAL_CHUNKS; T++) {
        cp_wait<1>();        // own copies of chunk T's group complete
        __syncthreads();     // cross-thread visibility of chunk T + slot bufS drained

        if (T + 2 < TOTAL_CHUNKS) stage_T(smem, bufS, T + 2, Xbase, tid);
        cp_commit();         // keep group counts aligned

        const uint32_t* As = (const uint32_t*)(smem + (size_t)bufR * STAGE_HALVES * 2);
        const uint32_t* Bs = As + A_HALVES / 2;

#pragma unroll
        for (int k16 = 0; k16 < 4; k16++) {     // four m16n8k16 steps cover 64 k
            const int ko = k16 * 8;             // u32 offset within row
            uint32_t a[4][4], b[8][2];
#pragma unroll
            for (int mt = 0; mt < 4; mt++) {
                const int r0 = (wm * 64 + mt * 16 + ar) * (KPH / 2) + ko + ak;
                a[mt][0] = As[r0];
                a[mt][1] = As[r0 + 8 * (KPH / 2)];
                a[mt][2] = As[r0 + 4];
                a[mt][3] = As[r0 + 8 * (KPH / 2) + 4];
            }
#pragma unroll
            for (int nt = 0; nt < 8; nt++) {
                const int nb = (wn * 64 + nt * 8 + ar) * (KPH / 2) + ko + ak;
                b[nt][0] = Bs[nb];
                b[nt][1] = Bs[nb + 4];
            }
#pragma unroll
            for (int mt = 0; mt < 4; mt++)
#pragma unroll
                for (int nt = 0; nt < 8; nt++)
                    mma_f16(acc[mt][nt], a[mt], b[nt]);
        }

        // ---- pass boundary: epilogue (registers + L2 table reads; no barrier) ----
        if ((T & (NCHUNK - 1)) == NCHUNK - 1) {
            const int p = T >> 4;
#pragma unroll
            for (int mt = 0; mt < 4; mt++) {
#pragma unroll
                for (int nt = 0; nt < 8; nt++) {
                    const int gn = p * N_TILE + wn * 64 + nt * 8 + 2 * ak;
                    const float4 w = __ldg(&vt4[gn >> 1]);   // {v0, t20, v1, t21}
                    racc[mt * 2] += w.x * tanh_fast(acc[mt][nt][0] + w.y)
                                  + w.z * tanh_fast(acc[mt][nt][1] + w.w);
                    racc[mt * 2 + 1] += w.x * tanh_fast(acc[mt][nt][2] + w.y)
                                      + w.z * tanh_fast(acc[mt][nt][3] + w.w);
                    acc[mt][nt][0] = 0.f; acc[mt][nt][1] = 0.f;
                    acc[mt][nt][2] = 0.f; acc[mt][nt][3] = 0.f;
                }
            }
        }

        bufR = (bufR == 2) ? 0 : bufR + 1;
        bufS = (bufS == 2) ? 0 : bufS + 1;
    }

    // reduce over the 4 lanes of each column group
#pragma unroll
    for (int j = 0; j < 8; j++) {
        racc[j] += __shfl_xor_sync(0xFFFFFFFFu, racc[j], 1);
        racc[j] += __shfl_xor_sync(0xFFFFFFFFu, racc[j], 2);
    }
    if (ak == 0) {
#pragma unroll
        for (int j = 0; j < 8; j++) {
            const int row = wm * 64 + (j >> 1) * 16 + ar + (j & 1) * 8;
            atomicAdd(&part[row], racc[j]);
        }
    }
    __syncthreads();
    if (tid < M_TILE) out[m0 + tid] = part[tid];
}

// ---------------- launch ----------------
extern "C" void kernel_launch(void* const* d_in, const int* in_sizes, int n_in,
                              void* d_out, int out_size) {
    const float* X  = (const float*)d_in[0];   // inputs [B,S,D]
    const float* g  = (const float*)d_in[1];   // g [B,D]
    const float* WO = (const float*)d_in[2];   // WO [SIZE,D]
    const float* WG = (const float*)d_in[3];   // WG [SIZE,D]
    const float* v  = (const float*)d_in[4];   // v [1,SIZE]
    float* out = (float*)d_out;

    __half* Xh;  cudaGetSymbolAddress((void**)&Xh,  g_Xh);
    __half* WOh; cudaGetSymbolAddress((void**)&WOh, g_WOh);

    cudaFuncSetAttribute(fused_kernel, cudaFuncAttributeMaxDynamicSharedMemorySize, SMEM_BYTES);

    const int nX4 = BB * SEQ * DD / 4;
    tohalf_kernel<<<nX4 / 256, 256>>>(X, (uint2*)Xh, nX4);
    const int nW4 = SZ * DD / 4;
    tohalf_kernel<<<nW4 / 256, 256>>>(WO, (uint2*)WOh, nW4);
    term2_kernel<<<dim3(SZ / 8, BB), 256>>>(WG, g, v);

    fused_kernel<<<(BB * SEQ) / M_TILE, THREADS, SMEM_BYTES>>>(out);
}